// round 1
// baseline (speedup 1.0000x reference)
#include <cuda_runtime.h>

// Problem constants (fixed by the reference)
#define NIN   4096
#define NOUT  1024
#define BC    128        // B * C_IN = 4 * 32
#define B_DIM 4
#define C_DIM 32

// Scratch: transposed features (N_IN, 128) and transposed accumulator (N_OUT, 128).
// float4 arrays guarantee 16B alignment for LDG.128 / red.v4.
__device__ float4 g_feat_t4[NIN * (BC / 4)];   // 2 MB
__device__ float4 g_agg_t4[NOUT * (BC / 4)];   // 512 KB

// ---------------------------------------------------------------------------
// Kernel A: transpose features (B,C,N)->(N,BC) and zero agg_t.
// tid covers 524288 elements; reads coalesced along n.
// ---------------------------------------------------------------------------
__global__ void qc_transpose_zero(const float* __restrict__ features) {
    int tid = blockIdx.x * blockDim.x + threadIdx.x;   // 0 .. 524287
    float* feat_t = reinterpret_cast<float*>(g_feat_t4);
    float* agg_t  = reinterpret_cast<float*>(g_agg_t4);

    if (tid < NOUT * BC) agg_t[tid] = 0.0f;

    int bc = tid >> 12;           // / NIN
    int n  = tid & (NIN - 1);     // % NIN
    feat_t[n * BC + bc] = features[tid];
}

// ---------------------------------------------------------------------------
// Kernel B: scatter. One warp per edge.
// lane l: float4 at feat_t[idx_in[e]*128 + 4l] -> red.add.v4 into agg_t row.
// Whole warp load = 512B contiguous (coalesced); RED row = 512B contiguous.
// ---------------------------------------------------------------------------
__global__ void qc_scatter(const int* __restrict__ idx_out,
                           const int* __restrict__ idx_in,
                           int E) {
    int gtid = blockIdx.x * blockDim.x + threadIdx.x;
    int warp = gtid >> 5;
    int lane = gtid & 31;
    if (warp >= E) return;

    int ii = __ldg(idx_in  + warp);   // broadcast load (all lanes same addr)
    int io = __ldg(idx_out + warp);

    float4 v = g_feat_t4[ii * (BC / 4) + lane];
    float4* dst = &g_agg_t4[io * (BC / 4) + lane];

    asm volatile("red.global.add.v4.f32 [%0], {%1,%2,%3,%4};"
                 :: "l"(dst), "f"(v.x), "f"(v.y), "f"(v.z), "f"(v.w)
                 : "memory");
}

// ---------------------------------------------------------------------------
// Kernel C: channel GEMM + layout restore.
// out[b, oc, o] = sum_i G[oc,i] * agg_t[o, b*32 + i]
// warp per (o,b); lane = oc. agg row read is one coalesced 128B load.
// G staged in shared, transposed (Gs[i*32+oc]) for conflict-free LDS.
// ---------------------------------------------------------------------------
__global__ void qc_gemm(const float* __restrict__ G, float* __restrict__ out) {
    __shared__ float Gs[C_DIM * C_DIM];   // Gs[i*32 + oc] = G[oc*32 + i]

    // Stage G transposed (1024 elements, blockDim = 256)
    for (int t = threadIdx.x; t < C_DIM * C_DIM; t += blockDim.x) {
        int oc = t >> 5;
        int i  = t & 31;
        Gs[i * C_DIM + oc] = G[t];
    }
    __syncthreads();

    int gtid = blockIdx.x * blockDim.x + threadIdx.x;
    int warp = gtid >> 5;          // 0 .. 4095
    int lane = gtid & 31;          // oc
    if (warp >= NOUT * B_DIM) return;

    int o = warp >> 2;             // output position
    int b = warp & 3;              // batch

    const float* agg_t = reinterpret_cast<const float*>(g_agg_t4);
    float a = agg_t[o * BC + b * C_DIM + lane];   // lane-th input channel

    float sum = 0.0f;
    #pragma unroll
    for (int i = 0; i < C_DIM; i++) {
        float av = __shfl_sync(0xffffffffu, a, i);
        sum = fmaf(Gs[i * C_DIM + lane], av, sum);
    }

    out[b * (C_DIM * NOUT) + lane * NOUT + o] = sum;
}

// ---------------------------------------------------------------------------
extern "C" void kernel_launch(void* const* d_in, const int* in_sizes, int n_in,
                              void* d_out, int out_size) {
    const float* features = (const float*)d_in[0];   // (4,32,4096) f32
    const float* G        = (const float*)d_in[1];   // (32,32)     f32
    const int*   idx_out  = (const int*)d_in[2];     // (E,) i32
    const int*   idx_in   = (const int*)d_in[3];     // (E,) i32
    float*       out      = (float*)d_out;           // (4,32,1024) f32
    int E = in_sizes[2];

    // A: transpose + zero (524288 threads)
    qc_transpose_zero<<<(B_DIM * C_DIM * NIN) / 256, 256>>>(features);

    // B: scatter, one warp per edge
    {
        long long threads = (long long)E * 32;
        int blocks = (int)((threads + 255) / 256);
        qc_scatter<<<blocks, 256>>>(idx_out, idx_in, E);
    }

    // C: GEMM, warp per (o,b) = 4096 warps
    qc_gemm<<<(NOUT * B_DIM * 32) / 256, 256>>>(G, out);
}